// round 2
// baseline (speedup 1.0000x reference)
#include <cuda_runtime.h>
#include <math.h>

#define SQ   4096
#define DD   512
#define VV   32000
#define HH   50
#define GHX  150
#define EMBD 10
#define XIN  (DD + VV)

#define NBE  128   // encoder blocks
#define NPB  4     // neurons per block (512/128)
#define RPB  12    // gate rows per block per matrix (3*NPB)

#define NBD  128   // decoder blocks
#define VPB  250   // vocab cols per block (32000/128)
#define VPBP 256   // padded

// ---------------- device scratch (no cudaMalloc allowed) ----------------
__device__ float g_h0[2][DD];
__device__ float g_h1[2][DD];
__device__ float g_dense_gi[GHX];
__device__ float g_tWhh1[HH * GHX];
__device__ float g_tWih2[HH * GHX];
__device__ float g_tWhh2[HH * GHX];
__device__ float g_ugfb[GHX];
__device__ float g_Zacc;
__device__ float g_rZ;
__device__ float g_h2vec[HH];
__device__ unsigned int g_barE;
__device__ unsigned int g_barD;

__device__ __forceinline__ float sigm(float x) { return 1.f / (1.f + expf(-x)); }

// Monotonic-counter grid barrier. All CTAs are guaranteed co-resident
// (grid <= #SMs, 1 CTA/SM by smem). release-arrive + acquire-spin.
__device__ __forceinline__ void grid_bar(unsigned int* ctr, unsigned int target) {
    __syncthreads();
    if (threadIdx.x == 0) {
        asm volatile("red.release.gpu.add.u32 [%0], %1;" :: "l"(ctr), "r"(1u) : "memory");
        unsigned int v;
        do {
            asm volatile("ld.acquire.gpu.u32 %0, [%1];" : "=r"(v) : "l"(ctr) : "memory");
        } while (v < target);
    }
    __syncthreads();
}

// ---------------- init: zero state, reset barriers, transpose small dec weights ----
__global__ void k_init(const float* __restrict__ dWhh1,
                       const float* __restrict__ dWih2,
                       const float* __restrict__ dWhh2) {
    int t = blockIdx.x * blockDim.x + threadIdx.x;
    if (t == 0) { g_barE = 0u; g_barD = 0u; g_Zacc = 1.f; g_rZ = 1.f; }
    if (t < DD) { g_h0[0][t] = 0.f; g_h0[1][t] = 0.f; g_h1[0][t] = 0.f; g_h1[1][t] = 0.f; }
    if (t < GHX) g_ugfb[t] = 0.f;
    if (t < HH * GHX) {
        int c = t / GHX, g = t % GHX;           // transposed layout [c][g]
        g_tWhh1[t] = dWhh1[g * HH + c];
        g_tWih2[t] = dWih2[g * HH + c];
        g_tWhh2[t] = dWhh2[g * HH + c];
    }
}

// ---------------- encoder: persistent, 1 barrier per time step ----------------
// Block b owns neurons n in [b*4, b*4+4). Phase k computes h1_k (layer1 from
// h0_k, h1_{k-1}) AND h0_{k+1} (layer0 from x_{k+1}, h0_k): both need only h0_k.
__global__ void __launch_bounds__(256, 1) k_encoder(
    const int*   __restrict__ input_mol, const float* __restrict__ emb,
    const float* __restrict__ eWih0, const float* __restrict__ eWhh0,
    const float* __restrict__ ebih0, const float* __restrict__ ebhh0,
    const float* __restrict__ eWih1, const float* __restrict__ eWhh1,
    const float* __restrict__ ebih1, const float* __restrict__ ebhh1)
{
    extern __shared__ float sm[];
    float* sWhh0 = sm;                      // [12][512]
    float* sWih1 = sWhh0 + RPB * DD;        // [12][512]
    float* sWhh1 = sWih1 + RPB * DD;        // [12][512]
    float* sWih0 = sWhh1 + RPB * DD;        // [12][16]
    float* sb    = sWih0 + RPB * 16;        // bih0[12] bhh0[12] bih1[12] bhh1[12]
    float* h0s   = sb + 48;                 // [512]
    float* h1s   = h0s + DD;                // [512]
    float* dots  = h1s + DD;                // [36]
    float* xs    = dots + 36;               // [16]

    const int b = blockIdx.x, tid = threadIdx.x;

    // load owned weight rows: local row lr = gate*4 + q -> global row gate*512 + b*4 + q
    for (int lr = 0; lr < RPB; lr++) {
        int gr = (lr >> 2) * DD + b * NPB + (lr & 3);
        for (int c = tid; c < DD; c += 256) {
            sWhh0[lr * DD + c] = eWhh0[gr * DD + c];
            sWih1[lr * DD + c] = eWih1[gr * DD + c];
            sWhh1[lr * DD + c] = eWhh1[gr * DD + c];
        }
        if (tid < EMBD) sWih0[lr * 16 + tid] = eWih0[gr * EMBD + tid];
        if (tid == 0) {
            sb[lr]      = ebih0[gr];
            sb[12 + lr] = ebhh0[gr];
            sb[24 + lr] = ebih1[gr];
            sb[36 + lr] = ebhh1[gr];
        }
    }
    if (tid < EMBD) xs[tid] = emb[input_mol[0] * EMBD + tid];
    __syncthreads();

    unsigned int epoch = 0;

    // prologue: h0_0 = gru(x_0, 0)
    if (tid < NPB) {
        int q = tid;
        float gir = sb[q], giz = sb[4 + q], gin = sb[8 + q];
        #pragma unroll
        for (int c = 0; c < EMBD; c++) {
            float xv = xs[c];
            gir += sWih0[q * 16 + c] * xv;
            giz += sWih0[(4 + q) * 16 + c] * xv;
            gin += sWih0[(8 + q) * 16 + c] * xv;
        }
        float r = sigm(gir + sb[12 + q]);
        float z = sigm(giz + sb[16 + q]);
        float n = tanhf(gin + r * sb[20 + q]);
        g_h0[0][b * NPB + q] = (1.f - z) * n;
    }
    grid_bar(&g_barE, NBE * (++epoch));

    for (int k = 0; k < SQ; k++) {
        const int cur = k & 1, nxt = cur ^ 1;
        for (int c = tid; c < DD; c += 256) {
            h0s[c] = g_h0[cur][c];
            h1s[c] = g_h1[nxt][c];            // h1_{k-1}
        }
        if (k + 1 < SQ && tid < EMBD) xs[tid] = emb[input_mol[k + 1] * EMBD + tid];
        __syncthreads();

        // 36 warp dot-tasks over 512 elems each
        const int w = tid >> 5, lane = tid & 31;
        for (int tau = w; tau < 36; tau += 8) {
            int m = tau / 12, lr = tau % 12;
            const float* wr = (m == 0 ? sWhh0 : (m == 1 ? sWih1 : sWhh1)) + lr * DD;
            const float* v  = (m == 2) ? h1s : h0s;
            float acc = 0.f;
            #pragma unroll
            for (int i = 0; i < 16; i++) acc += wr[i * 32 + lane] * v[i * 32 + lane];
            #pragma unroll
            for (int o = 16; o; o >>= 1) acc += __shfl_xor_sync(0xffffffffu, acc, o);
            if (lane == 0) dots[tau] = acc;   // [0..11]=Whh0.h0 [12..23]=Wih1.h0 [24..35]=Whh1.h1
        }
        __syncthreads();

        if (tid < NPB) {
            int q = tid, n_idx = b * NPB + q;
            // layer1: h1_k
            {
                float r = sigm(dots[12 + q]     + sb[24 + q] + dots[24 + q]     + sb[36 + q]);
                float z = sigm(dots[12 + 4 + q] + sb[28 + q] + dots[24 + 4 + q] + sb[40 + q]);
                float n = tanhf(dots[12 + 8 + q] + sb[32 + q] + r * (dots[24 + 8 + q] + sb[44 + q]));
                g_h1[cur][n_idx] = (1.f - z) * n + z * h1s[n_idx];
            }
            // layer0: h0_{k+1}
            if (k + 1 < SQ) {
                float gir = sb[q], giz = sb[4 + q], gin = sb[8 + q];
                #pragma unroll
                for (int c = 0; c < EMBD; c++) {
                    float xv = xs[c];
                    gir += sWih0[q * 16 + c] * xv;
                    giz += sWih0[(4 + q) * 16 + c] * xv;
                    gin += sWih0[(8 + q) * 16 + c] * xv;
                }
                float r = sigm(gir + dots[q]     + sb[12 + q]);
                float z = sigm(giz + dots[4 + q] + sb[16 + q]);
                float n = tanhf(gin + r * (dots[8 + q] + sb[20 + q]));
                g_h0[nxt][n_idx] = (1.f - z) * n + z * h0s[n_idx];
            }
        }
        grid_bar(&g_barE, NBE * (++epoch));
    }
}

// ---------------- mid: dense part of decoder layer-1 input gates (constant) ----
__global__ void k_mid(const float* __restrict__ dWih1, const float* __restrict__ dbih1) {
    const float* dense = g_h1[(SQ - 1) & 1];
    int g = threadIdx.x;
    if (g < GHX) {
        float acc = dbih1[g];
        const float* row = dWih1 + (size_t)g * XIN;
        for (int c = 0; c < DD; c++) acc += row[c] * dense[c];
        g_dense_gi[g] = acc;
    }
}

// ---------------- decoder: persistent, 2 barriers per time step ----------------
// Block b owns vocab [b*250, b*250+250). Phase B (block 0): tiny GRUs from the
// reduced (unnormalized) feedback accumulator + Z. Phase AC (all): logits,
// e=exp, Z-partial, unnormalized fb-matvec partials; output of step t-1
// normalized with rZ computed in B.
__global__ void __launch_bounds__(256, 1) k_decoder(
    const float* __restrict__ dWih1,
    const float* __restrict__ dbhh1, const float* __restrict__ dbih2,
    const float* __restrict__ dbhh2,
    const float* __restrict__ W2, const float* __restrict__ b2,
    float* __restrict__ out)
{
    extern __shared__ float sm[];
    float* Wfb    = sm;                       // [150][256]
    float* W2t    = Wfb  + GHX * VPBP;        // [50][256]
    float* es     = W2t  + HH * VPBP;         // [256]
    float* h2s    = es   + VPBP;              // [64]
    float* gia    = h2s  + 64;                // [150]
    float* gha    = gia  + GHX;               // [150]
    float* h1s    = gha  + GHX;               // [64]
    float* h2os   = h1s  + 64;                // [64]
    float* red    = h2os + 64;                // [8]
    float* sdbhh1 = red  + 8;                 // [150]
    float* sdbih2 = sdbhh1 + GHX;             // [150]
    float* sdbhh2 = sdbih2 + GHX;             // [150]

    const int b = blockIdx.x, tid = threadIdx.x;
    const int j0 = b * VPB;

    for (int idx = tid; idx < GHX * VPBP; idx += 256) {
        int r = idx / VPBP, c = idx % VPBP;
        Wfb[idx] = (c < VPB) ? dWih1[(size_t)r * XIN + DD + j0 + c] : 0.f;
    }
    for (int idx = tid; idx < HH * VPBP; idx += 256) {
        int c = idx / VPBP, j = idx % VPBP;
        W2t[idx] = (j < VPB) ? W2[(size_t)(j0 + j) * HH + c] : 0.f;
    }
    if (tid < GHX) { sdbhh1[tid] = dbhh1[tid]; sdbih2[tid] = dbih2[tid]; sdbhh2[tid] = dbhh2[tid]; }
    if (b == 0 && tid < HH) { h1s[tid] = 0.f; h2os[tid] = 0.f; }
    es[tid] = 0.f;
    const float b2r = (tid < VPB) ? b2[j0 + tid] : 0.f;
    __syncthreads();

    float eprev = 0.f;
    unsigned int epoch = 0;

    for (int t = 0; t < SQ; t++) {
        // -------- phase B: block 0 serial small GRUs --------
        if (b == 0) {
            float rZ = 1.f / g_Zacc;
            if (tid < GHX) {
                int g = tid;
                float gi = g_dense_gi[g] + g_ugfb[g] * rZ;
                float gh = sdbhh1[g];
                #pragma unroll
                for (int c = 0; c < HH; c++) gh += g_tWhh1[c * GHX + g] * h1s[c];
                gia[g] = gi; gha[g] = gh;
                g_ugfb[g] = 0.f;
            }
            if (tid == 0) { g_rZ = rZ; g_Zacc = 0.f; }
            __syncthreads();
            if (tid < HH) {
                int c = tid;
                float r = sigm(gia[c] + gha[c]);
                float z = sigm(gia[HH + c] + gha[HH + c]);
                float n = tanhf(gia[2 * HH + c] + r * gha[2 * HH + c]);
                h1s[c] = (1.f - z) * n + z * h1s[c];
            }
            __syncthreads();
            if (tid < GHX) {
                int g = tid;
                float gi = sdbih2[g], gh = sdbhh2[g];
                #pragma unroll
                for (int c = 0; c < HH; c++) {
                    gi += g_tWih2[c * GHX + g] * h1s[c];
                    gh += g_tWhh2[c * GHX + g] * h2os[c];
                }
                gia[g] = gi; gha[g] = gh;
            }
            __syncthreads();
            if (tid < HH) {
                int c = tid;
                float r = sigm(gia[c] + gha[c]);
                float z = sigm(gia[HH + c] + gha[HH + c]);
                float n = tanhf(gia[2 * HH + c] + r * gha[2 * HH + c]);
                float h2n = (1.f - z) * n + z * h2os[c];
                h2os[c] = h2n;
                g_h2vec[c] = h2n;
            }
        }
        grid_bar(&g_barD, NBD * (++epoch));

        // -------- phase AC: all blocks --------
        if (tid < HH) h2s[tid] = g_h2vec[tid];
        const float rZp = g_rZ;
        if (t > 0 && tid < VPB) out[(size_t)(t - 1) * VV + j0 + tid] = eprev * rZp;

        float e = 0.f;
        if (tid < VPB) {
            float acc = b2r;
            #pragma unroll
            for (int c = 0; c < HH; c++) acc += h2s[c] * W2t[c * VPBP + tid];
            // NOTE: h2s read below __syncthreads guard
            e = acc; // placeholder, finalized after sync
        }
        __syncthreads();            // h2s ready for everyone
        if (tid < VPB) {
            float acc = b2r;
            #pragma unroll
            for (int c = 0; c < HH; c++) acc += h2s[c] * W2t[c * VPBP + tid];
            e = expf(acc);
        }
        eprev = e;
        es[tid] = e;

        float zs = e;
        #pragma unroll
        for (int o = 16; o; o >>= 1) zs += __shfl_xor_sync(0xffffffffu, zs, o);
        if ((tid & 31) == 0) red[tid >> 5] = zs;
        __syncthreads();            // es + red ready
        if (tid == 0) {
            float z8 = red[0] + red[1] + red[2] + red[3] + red[4] + red[5] + red[6] + red[7];
            atomicAdd(&g_Zacc, z8);
        }
        // unnormalized feedback matvec: ugfb[r] += sum_j Wfb[r][j] * e[j]
        const int w = tid >> 5, lane = tid & 31;
        for (int r = w; r < GHX; r += 8) {
            const float* wr = Wfb + r * VPBP;
            float acc = 0.f;
            #pragma unroll
            for (int i = 0; i < 8; i++) acc += wr[i * 32 + lane] * es[i * 32 + lane];
            #pragma unroll
            for (int o = 16; o; o >>= 1) acc += __shfl_xor_sync(0xffffffffu, acc, o);
            if (lane == 0) atomicAdd(&g_ugfb[r], acc);
        }
        grid_bar(&g_barD, NBD * (++epoch));
    }

    // epilogue: normalize last step's outputs (Zacc complete after final barrier)
    if (tid < VPB) out[(size_t)(SQ - 1) * VV + j0 + tid] = eprev / g_Zacc;
}

// ---------------- launcher ----------------
extern "C" void kernel_launch(void* const* d_in, const int* in_sizes, int n_in,
                              void* d_out, int out_size) {
    const int*   input_mol = (const int*)  d_in[0];
    const float* emb   = (const float*)d_in[1];
    const float* eWih0 = (const float*)d_in[2];
    const float* eWhh0 = (const float*)d_in[3];
    const float* ebih0 = (const float*)d_in[4];
    const float* ebhh0 = (const float*)d_in[5];
    const float* eWih1 = (const float*)d_in[6];
    const float* eWhh1 = (const float*)d_in[7];
    const float* ebih1 = (const float*)d_in[8];
    const float* ebhh1 = (const float*)d_in[9];
    const float* dWih1 = (const float*)d_in[10];
    const float* dWhh1 = (const float*)d_in[11];
    const float* dbih1 = (const float*)d_in[12];
    const float* dbhh1 = (const float*)d_in[13];
    const float* dWih2 = (const float*)d_in[14];
    const float* dWhh2 = (const float*)d_in[15];
    const float* dbih2 = (const float*)d_in[16];
    const float* dbhh2 = (const float*)d_in[17];
    const float* W2    = (const float*)d_in[18];
    const float* b2    = (const float*)d_in[19];
    float* out = (float*)d_out;

    const size_t esmem = (size_t)(3 * RPB * DD + RPB * 16 + 48 + 2 * DD + 36 + 16) * sizeof(float);
    const size_t dsmem = (size_t)(GHX * VPBP + HH * VPBP + VPBP + 64 + 2 * GHX + 64 + 64 + 8 + 3 * GHX) * sizeof(float);

    cudaFuncSetAttribute(k_encoder, cudaFuncAttributeMaxDynamicSharedMemorySize, (int)esmem);
    cudaFuncSetAttribute(k_decoder, cudaFuncAttributeMaxDynamicSharedMemorySize, (int)dsmem);

    k_init<<<32, 256>>>(dWhh1, dWih2, dWhh2);
    k_encoder<<<NBE, 256, esmem>>>(input_mol, emb, eWih0, eWhh0, ebih0, ebhh0,
                                   eWih1, eWhh1, ebih1, ebhh1);
    k_mid<<<1, 256>>>(dWih1, dbih1);
    k_decoder<<<NBD, 256, dsmem>>>(dWih1, dbhh1, dbih2, dbhh2, W2, b2, out);
}

// round 3
// speedup vs baseline: 1.2368x; 1.2368x over previous
#include <cuda_runtime.h>
#include <cuda_fp16.h>
#include <math.h>

#define SQ   4096
#define DD   512
#define VV   32000
#define HH   50
#define GHX  150
#define GHXP 160
#define EMBD 10
#define XIN  (DD + VV)

#define NBE  128   // encoder blocks
#define NPB  4     // neurons per block
#define RPB  12    // gate rows per block per matrix

#define NBD  128   // decoder blocks
#define VPB  250   // vocab cols per block
#define VPBP 256   // padded

// ---------------- device scratch ----------------
__device__ __align__(16) float g_h0[2][DD];
__device__ __align__(16) float g_h1[2][DD];
__device__ float g_dense_gi[GHX];
__device__ float g_ugfb[GHX];
__device__ float g_Zacc;
__device__ float g_rZ;
__device__ float g_h2vec[HH];

struct __align__(128) PadCtr { unsigned int v; unsigned int pad[31]; };
__device__ PadCtr g_cntE, g_flagE, g_cntD, g_flagD;

__device__ __forceinline__ float sigm(float x) { return 1.f / (1.f + __expf(-x)); }

__device__ __forceinline__ void p_arrive(unsigned int* c) {
    asm volatile("red.release.gpu.add.u32 [%0], %1;" :: "l"(c), "r"(1u) : "memory");
}
__device__ __forceinline__ void p_wait_ge(unsigned int* p, unsigned int tgt) {
    unsigned int v;
    do { asm volatile("ld.acquire.gpu.u32 %0, [%1];" : "=r"(v) : "l"(p) : "memory"); }
    while (v < tgt);
}
__device__ __forceinline__ void p_publish(unsigned int* p, unsigned int val) {
    asm volatile("st.release.gpu.u32 [%0], %1;" :: "l"(p), "r"(val) : "memory");
}

// flag-split grid barrier: arrivals on one line, release flag on another.
__device__ __forceinline__ void bar_flag(unsigned int* cnt, unsigned int* flag,
                                         unsigned int epoch, unsigned int nb) {
    __syncthreads();
    if (threadIdx.x == 0) {
        p_arrive(cnt);
        if (blockIdx.x == 0) { p_wait_ge(cnt, epoch * nb); p_publish(flag, epoch); }
        else                 { p_wait_ge(flag, epoch); }
    }
    __syncthreads();
}

// 8-half dot with fp32 accumulation
__device__ __forceinline__ float dot8h(uint4 a, uint4 b) {
    const __half2* pa = (const __half2*)&a;
    const __half2* pb = (const __half2*)&b;
    float acc = 0.f;
    #pragma unroll
    for (int i = 0; i < 4; i++) {
        float2 x = __half22float2(pa[i]);
        float2 y = __half22float2(pb[i]);
        acc += x.x * y.x + x.y * y.y;
    }
    return acc;
}

// ---------------- init ----------------
__global__ void k_init() {
    int t = blockIdx.x * blockDim.x + threadIdx.x;
    if (t == 0) {
        g_cntE.v = 0u; g_flagE.v = 0u; g_cntD.v = 0u; g_flagD.v = 0u;
        g_Zacc = 1.f; g_rZ = 1.f;
    }
    if (t < DD) { g_h0[0][t] = 0.f; g_h0[1][t] = 0.f; g_h1[0][t] = 0.f; g_h1[1][t] = 0.f; }
    if (t < GHX) g_ugfb[t] = 0.f;
}

// ---------------- encoder ----------------
__global__ void __launch_bounds__(256, 1) k_encoder(
    const int*   __restrict__ input_mol, const float* __restrict__ emb,
    const float* __restrict__ eWih0, const float* __restrict__ eWhh0,
    const float* __restrict__ ebih0, const float* __restrict__ ebhh0,
    const float* __restrict__ eWih1, const float* __restrict__ eWhh1,
    const float* __restrict__ ebih1, const float* __restrict__ ebhh1)
{
    extern __shared__ float sm[];
    float* sWhh0 = sm;                      // [12][512]
    float* sWih1 = sWhh0 + RPB * DD;        // [12][512]
    float* sWhh1 = sWih1 + RPB * DD;        // [12][512]
    float* sWih0 = sWhh1 + RPB * DD;        // [12][16]
    float* sb    = sWih0 + RPB * 16;        // 48
    float* h0s   = sb + 48;                 // [512]
    float* h1s   = h0s + DD;                // [512]
    float* dots  = h1s + DD;                // [36]
    float* xs    = dots + 36;               // [16]

    const int b = blockIdx.x, tid = threadIdx.x;

    for (int lr = 0; lr < RPB; lr++) {
        int gr = (lr >> 2) * DD + b * NPB + (lr & 3);
        for (int c = tid; c < DD; c += 256) {
            sWhh0[lr * DD + c] = eWhh0[gr * DD + c];
            sWih1[lr * DD + c] = eWih1[gr * DD + c];
            sWhh1[lr * DD + c] = eWhh1[gr * DD + c];
        }
        if (tid < EMBD) sWih0[lr * 16 + tid] = eWih0[gr * EMBD + tid];
        if (tid == 0) {
            sb[lr]      = ebih0[gr];
            sb[12 + lr] = ebhh0[gr];
            sb[24 + lr] = ebih1[gr];
            sb[36 + lr] = ebhh1[gr];
        }
    }
    if (tid < EMBD) xs[tid] = emb[input_mol[0] * EMBD + tid];
    __syncthreads();

    unsigned int epoch = 0;

    // prologue: h0_0
    if (tid < NPB) {
        int q = tid;
        float gir = sb[q], giz = sb[4 + q], gin = sb[8 + q];
        #pragma unroll
        for (int c = 0; c < EMBD; c++) {
            float xv = xs[c];
            gir += sWih0[q * 16 + c] * xv;
            giz += sWih0[(4 + q) * 16 + c] * xv;
            gin += sWih0[(8 + q) * 16 + c] * xv;
        }
        float r = sigm(gir + sb[12 + q]);
        float z = sigm(giz + sb[16 + q]);
        float n = tanhf(gin + r * sb[20 + q]);
        g_h0[0][b * NPB + q] = (1.f - z) * n;
    }
    bar_flag(&g_cntE.v, &g_flagE.v, ++epoch, NBE);

    for (int k = 0; k < SQ; k++) {
        const int cur = k & 1, nxt = cur ^ 1;
        if (tid < 128)      ((float4*)h0s)[tid]       = ((const float4*)g_h0[cur])[tid];
        else                ((float4*)h1s)[tid - 128] = ((const float4*)g_h1[nxt])[tid - 128];
        if (k + 1 < SQ && tid < EMBD) xs[tid] = emb[input_mol[k + 1] * EMBD + tid];
        __syncthreads();

        const int w = tid >> 5, lane = tid & 31;
        for (int tau = w; tau < 36; tau += 8) {
            int m = tau / 12, lr = tau % 12;
            const float* wr = (m == 0 ? sWhh0 : (m == 1 ? sWih1 : sWhh1)) + lr * DD;
            const float* v  = (m == 2) ? h1s : h0s;
            const float4* w4 = (const float4*)wr;
            const float4* v4 = (const float4*)v;
            float acc = 0.f;
            #pragma unroll
            for (int i = 0; i < 4; i++) {
                float4 a = w4[i * 32 + lane];
                float4 x = v4[i * 32 + lane];
                acc += a.x * x.x + a.y * x.y + a.z * x.z + a.w * x.w;
            }
            #pragma unroll
            for (int o = 16; o; o >>= 1) acc += __shfl_xor_sync(0xffffffffu, acc, o);
            if (lane == 0) dots[tau] = acc;
        }
        __syncthreads();

        if (tid < NPB) {
            int q = tid, n_idx = b * NPB + q;
            {   // layer1: h1_k
                float r = sigm(dots[12 + q]     + sb[24 + q] + dots[24 + q]     + sb[36 + q]);
                float z = sigm(dots[12 + 4 + q] + sb[28 + q] + dots[24 + 4 + q] + sb[40 + q]);
                float n = tanhf(dots[12 + 8 + q] + sb[32 + q] + r * (dots[24 + 8 + q] + sb[44 + q]));
                g_h1[cur][n_idx] = (1.f - z) * n + z * h1s[n_idx];
            }
            if (k + 1 < SQ) {   // layer0: h0_{k+1}
                float gir = sb[q], giz = sb[4 + q], gin = sb[8 + q];
                #pragma unroll
                for (int c = 0; c < EMBD; c++) {
                    float xv = xs[c];
                    gir += sWih0[q * 16 + c] * xv;
                    giz += sWih0[(4 + q) * 16 + c] * xv;
                    gin += sWih0[(8 + q) * 16 + c] * xv;
                }
                float r = sigm(gir + dots[q]     + sb[12 + q]);
                float z = sigm(giz + dots[4 + q] + sb[16 + q]);
                float n = tanhf(gin + r * (dots[8 + q] + sb[20 + q]));
                g_h0[nxt][n_idx] = (1.f - z) * n + z * h0s[n_idx];
            }
        }
        bar_flag(&g_cntE.v, &g_flagE.v, ++epoch, NBE);
    }
}

// ---------------- mid ----------------
__global__ void k_mid(const float* __restrict__ dWih1, const float* __restrict__ dbih1) {
    const float* dense = g_h1[(SQ - 1) & 1];
    int g = threadIdx.x;
    if (g < GHX) {
        float acc = dbih1[g];
        const float* row = dWih1 + (size_t)g * XIN;
        for (int c = 0; c < DD; c++) acc += row[c] * dense[c];
        g_dense_gi[g] = acc;
    }
}

// ---------------- decoder: 1 counter-round per step ----------------
__global__ void __launch_bounds__(256, 1) k_decoder(
    const float* __restrict__ dWih1,
    const float* __restrict__ dWhh1, const float* __restrict__ dWih2,
    const float* __restrict__ dWhh2,
    const float* __restrict__ dbhh1, const float* __restrict__ dbih2,
    const float* __restrict__ dbhh2,
    const float* __restrict__ W2, const float* __restrict__ b2,
    float* __restrict__ out)
{
    extern __shared__ float smf[];
    __half* WfbH = (__half*)smf;                    // [150][256] halves
    __half* W2tH = WfbH + GHX * VPBP;               // [50][256] halves
    float*  tW1  = (float*)(W2tH + HH * VPBP);      // [50][160] Whh1^T
    float*  tW2i = tW1  + HH * GHXP;                // [50][160] Wih2^T
    float*  tW2h = tW2i + HH * GHXP;                // [50][160] Whh2^T
    __half* esh  = (__half*)(tW2h + HH * GHXP);     // [256] halves (16B aligned)
    float*  fp   = (float*)(esh + VPBP);
    float*  h2s  = fp;            fp += 64;
    float*  h1s  = fp;            fp += 64;
    float*  h2os = fp;            fp += 64;
    float*  gia  = fp;            fp += GHX;
    float*  gha  = fp;            fp += GHX;
    float*  sgi  = fp;            fp += GHX;
    float*  sb1  = fp;            fp += GHX;
    float*  sb2i = fp;            fp += GHX;
    float*  sb2h = fp;            fp += GHX;
    float*  rzbuf = fp;           fp += 4;
    float*  zred  = fp;           fp += 8;

    const int b = blockIdx.x, tid = threadIdx.x;
    const int j0 = b * VPB;
    const int w = tid >> 5, lane = tid & 31;

    for (int idx = tid; idx < GHX * VPBP; idx += 256) {
        int r = idx / VPBP, c = idx % VPBP;
        WfbH[idx] = __float2half((c < VPB) ? dWih1[(size_t)r * XIN + DD + j0 + c] : 0.f);
    }
    for (int idx = tid; idx < HH * VPBP; idx += 256) {
        int c = idx / VPBP, j = idx % VPBP;
        W2tH[idx] = __float2half((j < VPB) ? W2[(size_t)(j0 + j) * HH + c] : 0.f);
    }
    if (b == 0) {
        for (int idx = tid; idx < HH * GHX; idx += 256) {
            int g = idx / HH, c = idx % HH;
            tW1 [c * GHXP + g] = dWhh1[idx];
            tW2i[c * GHXP + g] = dWih2[idx];
            tW2h[c * GHXP + g] = dWhh2[idx];
        }
        if (tid < GHX) { sb1[tid] = dbhh1[tid]; sb2i[tid] = dbih2[tid]; sb2h[tid] = dbhh2[tid];
                         sgi[tid] = g_dense_gi[tid]; }
        if (tid < HH)  { h1s[tid] = 0.f; h2os[tid] = 0.f; }
    }
    const float b2r = (tid < VPB) ? b2[j0 + tid] : 0.f;
    __syncthreads();

    float eprev = 0.f;

    for (int t = 0; t < SQ; t++) {
        if (b == 0) {
            // ---- serial phase B (this block is the coordinator) ----
            if (tid == 0) {
                if (t > 0) p_wait_ge(&g_cntD.v, (unsigned)(NBD * t));
                float rz = 1.f / g_Zacc;
                rzbuf[0] = rz; g_rZ = rz; g_Zacc = 0.f;
            }
            __syncthreads();
            const float rz = rzbuf[0];
            if (tid < GHX) {
                float gi = sgi[tid] + g_ugfb[tid] * rz;  g_ugfb[tid] = 0.f;
                float gh = sb1[tid];
                #pragma unroll
                for (int c = 0; c < HH; c++) gh += tW1[c * GHXP + tid] * h1s[c];
                gia[tid] = gi; gha[tid] = gh;
            }
            __syncthreads();
            if (tid < HH) {
                float r = sigm(gia[tid] + gha[tid]);
                float z = sigm(gia[HH + tid] + gha[HH + tid]);
                float n = tanhf(gia[2 * HH + tid] + r * gha[2 * HH + tid]);
                h1s[tid] = (1.f - z) * n + z * h1s[tid];
            }
            __syncthreads();
            if (tid < GHX) {
                float gi = sb2i[tid], gh = sb2h[tid];
                #pragma unroll
                for (int c = 0; c < HH; c++) {
                    gi += tW2i[c * GHXP + tid] * h1s[c];
                    gh += tW2h[c * GHXP + tid] * h2os[c];
                }
                gia[tid] = gi; gha[tid] = gh;
            }
            __syncthreads();
            if (tid < HH) {
                float r = sigm(gia[tid] + gha[tid]);
                float z = sigm(gia[HH + tid] + gha[HH + tid]);
                float n = tanhf(gia[2 * HH + tid] + r * gha[2 * HH + tid]);
                float h2n = (1.f - z) * n + z * h2os[tid];
                h2os[tid] = h2n; h2s[tid] = h2n;
                g_h2vec[tid] = h2n;
            }
            __syncthreads();
            if (tid == 0) p_publish(&g_flagD.v, (unsigned)(t + 1));
        } else {
            if (tid == 0) p_wait_ge(&g_flagD.v, (unsigned)(t + 1));
            __syncthreads();
            if (tid < HH) h2s[tid] = g_h2vec[tid];
            if (tid == 0) rzbuf[0] = g_rZ;
            __syncthreads();
        }

        // ---- parallel phase (all blocks) ----
        if (t > 0 && tid < VPB)
            __stcs(&out[(size_t)(t - 1) * VV + j0 + tid], eprev * rzbuf[0]);

        float e = 0.f;
        if (tid < VPB) {
            float acc = b2r;
            #pragma unroll
            for (int c = 0; c < HH; c++) acc += h2s[c] * __half2float(W2tH[c * VPBP + tid]);
            e = __expf(acc);
        }
        eprev = e;
        esh[tid] = __float2half(e);

        float zs = e;
        #pragma unroll
        for (int o = 16; o; o >>= 1) zs += __shfl_xor_sync(0xffffffffu, zs, o);
        if (lane == 0) zred[w] = zs;
        __syncthreads();                         // esh + zred ready
        if (tid == 0) {
            float z8 = zred[0] + zred[1] + zred[2] + zred[3]
                     + zred[4] + zred[5] + zred[6] + zred[7];
            atomicAdd(&g_Zacc, z8);
        }

        // feedback matvec: es held in registers, weights streamed from smem
        const uint4 ev = ((const uint4*)esh)[lane];   // 8 halves of e per lane
        for (int r = w; r < GHX; r += 8) {
            uint4 wv = ((const uint4*)(WfbH + r * VPBP))[lane];
            float acc = dot8h(wv, ev);
            #pragma unroll
            for (int o = 16; o; o >>= 1) acc += __shfl_xor_sync(0xffffffffu, acc, o);
            if (lane == 0) atomicAdd(&g_ugfb[r], acc);
        }
        __syncthreads();
        if (tid == 0) p_arrive(&g_cntD.v);
    }

    // epilogue: final row normalization after all blocks' last Z arrives
    if (tid == 0) { p_wait_ge(&g_cntD.v, (unsigned)(NBD * SQ)); rzbuf[0] = 1.f / g_Zacc; }
    __syncthreads();
    if (tid < VPB)
        __stcs(&out[(size_t)(SQ - 1) * VV + j0 + tid], eprev * rzbuf[0]);
}

// ---------------- launcher ----------------
extern "C" void kernel_launch(void* const* d_in, const int* in_sizes, int n_in,
                              void* d_out, int out_size) {
    const int*   input_mol = (const int*)  d_in[0];
    const float* emb   = (const float*)d_in[1];
    const float* eWih0 = (const float*)d_in[2];
    const float* eWhh0 = (const float*)d_in[3];
    const float* ebih0 = (const float*)d_in[4];
    const float* ebhh0 = (const float*)d_in[5];
    const float* eWih1 = (const float*)d_in[6];
    const float* eWhh1 = (const float*)d_in[7];
    const float* ebih1 = (const float*)d_in[8];
    const float* ebhh1 = (const float*)d_in[9];
    const float* dWih1 = (const float*)d_in[10];
    const float* dWhh1 = (const float*)d_in[11];
    // d_in[12] = dbih1 (folded into k_mid)
    const float* dbih1 = (const float*)d_in[12];
    const float* dbhh1 = (const float*)d_in[13];
    const float* dWih2 = (const float*)d_in[14];
    const float* dWhh2 = (const float*)d_in[15];
    const float* dbih2 = (const float*)d_in[16];
    const float* dbhh2 = (const float*)d_in[17];
    const float* W2    = (const float*)d_in[18];
    const float* b2    = (const float*)d_in[19];
    float* out = (float*)d_out;

    const size_t esmem = (size_t)(3 * RPB * DD + RPB * 16 + 48 + 2 * DD + 36 + 16) * sizeof(float);
    const size_t dsmem = (size_t)(GHX * VPBP + HH * VPBP) * sizeof(__half)
                       + (size_t)(3 * HH * GHXP) * sizeof(float)
                       + (size_t)VPBP * sizeof(__half)
                       + (size_t)(3 * 64 + 6 * GHX + 4 + 8) * sizeof(float);

    cudaFuncSetAttribute(k_encoder, cudaFuncAttributeMaxDynamicSharedMemorySize, (int)esmem);
    cudaFuncSetAttribute(k_decoder, cudaFuncAttributeMaxDynamicSharedMemorySize, (int)dsmem);

    k_init<<<3, 256>>>();
    k_encoder<<<NBE, 256, esmem>>>(input_mol, emb, eWih0, eWhh0, ebih0, ebhh0,
                                   eWih1, eWhh1, ebih1, ebhh1);
    k_mid<<<1, 256>>>(dWih1, dbih1);
    k_decoder<<<NBD, 256, dsmem>>>(dWih1, dWhh1, dWih2, dWhh2,
                                   dbhh1, dbih2, dbhh2, W2, b2, out);
}